// round 14
// baseline (speedup 1.0000x reference)
#include <cuda_runtime.h>
#include <math.h>
#include <stdint.h>

#define NQ    20
#define NL    4
#define BATCH 16
#define DIM   (1 << NQ)

#define NSM      148
#define GRID1W   (NSM * 2)          // one full wave at 2 CTAs/SM
#define NUNITS   (BATCH * 64)       // work units per pass (1024)

__device__ float  g_bufA[BATCH * DIM];   // 64 MB
__device__ float  g_bufB[BATCH * DIM];   // 64 MB
__device__ float2 g_rf[NL * NQ];   // .x = ratio (|r|<=1), .y = form (0 or 1)
__device__ float  g_absC;          // |product of per-gate scales|

// ---------------------------------------------------------------------------
// Fast-Givens precompute.
//   form0 (|c|>=|s|): M = c*[[1,-t],[t,1]], t=s/c
//   form1 (|s|> |c|): M = s*[[u,-1],[1,u]], u=c/s
// ---------------------------------------------------------------------------
__global__ void sincos_kernel(const float* __restrict__ theta) {
    __shared__ float sc[NL * NQ];
    int i = threadIdx.x;
    if (i < NL * NQ) {
        float t = 0.5f * theta[i];
        float c = cosf(t), s = sinf(t);
        bool form = fabsf(s) > fabsf(c);
        g_rf[i] = make_float2(form ? (c / s) : (s / c), form ? 1.0f : 0.0f);
        sc[i] = form ? s : c;
    }
    __syncthreads();
    if (i == 0) {
        float p = 1.0f;
        for (int k = 0; k < NL * NQ; k++) p *= sc[k];
        g_absC = fabsf(p);
    }
}

// ---------------------------------------------------------------------------
// Fast-Givens butterflies. 'a' = role-0 element:
//   form0: a' = a - r*b ; b' = b + r*a
//   form1: a' = r*a - b ; b' = r*b + a
// ---------------------------------------------------------------------------
template <int N>
__device__ __forceinline__ void stage_fg(float* e, int m, float2 rf) {
    float r = rf.x;
    if (rf.y == 0.0f) {
#pragma unroll
        for (int j = 0; j < N; j++)
            if ((j & m) == 0) {
                float a = e[j], b = e[j | m];
                e[j]     = fmaf(-r, b, a);
                e[j | m] = fmaf( r, a, b);
            }
    } else {
#pragma unroll
        for (int j = 0; j < N; j++)
            if ((j & m) == 0) {
                float a = e[j], b = e[j | m];
                e[j]     = fmaf(r, a, -b);
                e[j | m] = fmaf(r, b,  a);
            }
    }
}

__device__ __forceinline__ float xsign(float v, uint32_t sg) {
    return __uint_as_float(__float_as_uint(v) ^ sg);
}

__device__ __forceinline__ void stage_xlane_fg(float e[32], int kbit, float2 rf, int lane) {
    int bit = (lane >> kbit) & 1;
    if (rf.y == 0.0f) {
        float rs = bit ? rf.x : -rf.x;
#pragma unroll
        for (int j = 0; j < 32; j++) {
            float o = __shfl_xor_sync(0xffffffffu, e[j], 1 << kbit);
            e[j] = fmaf(rs, o, e[j]);
        }
    } else {
        float r = rf.x;
        uint32_t sg = bit ? 0u : 0x80000000u;
#pragma unroll
        for (int j = 0; j < 32; j++) {
            float o = __shfl_xor_sync(0xffffffffu, e[j], 1 << kbit);
            e[j] = fmaf(r, e[j], xsign(o, sg));
        }
    }
}

// Conjugated H stage (P^-1 H P): couples u-pairs differing in bits {hb, hb-1};
// role(u) = parity(u >> hb).
template <int HB>
__device__ __forceinline__ void conj_stage(float e[64], float2 rf) {
    const int mask = 3 << (HB - 1);
    float r = rf.x;
    bool f1 = (rf.y != 0.0f);
    if (!f1) {
#pragma unroll
        for (int u = 0; u < 64; u++)
            if ((u & (1 << HB)) == 0) {
                int v = u ^ mask;
                int ra = __popc(u >> HB) & 1;
                int ia = ra ? v : u;
                int ib = ra ? u : v;
                float a = e[ia], b = e[ib];
                e[ia] = fmaf(-r, b, a);
                e[ib] = fmaf( r, a, b);
            }
    } else {
#pragma unroll
        for (int u = 0; u < 64; u++)
            if ((u & (1 << HB)) == 0) {
                int v = u ^ mask;
                int ra = __popc(u >> HB) & 1;
                int ia = ra ? v : u;
                int ib = ra ? u : v;
                float a = e[ia], b = e[ib];
                e[ia] = fmaf(r, a, -b);
                e[ib] = fmaf(r, b,  a);
            }
    }
}

// Conjugated R5(layer1) stage inside hh: couples g bits {14,13} = (reg bit 0,
// lane bit 0). Partner of e[u] is shfl_xor(e[u^1], 1). Role 'a' = parity(u)==0.
__device__ __forceinline__ void conj_r5_stage(float e[64], float2 rf) {
    float r = rf.x;
    bool f1 = (rf.y != 0.0f);
#pragma unroll
    for (int u = 0; u < 64; u += 2) {
        float o0 = __shfl_xor_sync(0xffffffffu, e[u + 1], 1);
        float o1 = __shfl_xor_sync(0xffffffffu, e[u],     1);
        bool aFirst = ((__popc(u) & 1) == 0);
        if (!f1) {
            if (aFirst) {
                e[u]     = fmaf(-r, o0, e[u]);
                e[u + 1] = fmaf( r, o1, e[u + 1]);
            } else {
                e[u]     = fmaf( r, o0, e[u]);
                e[u + 1] = fmaf(-r, o1, e[u + 1]);
            }
        } else {
            if (aFirst) {
                e[u]     = fmaf(r, e[u],     -o0);
                e[u + 1] = fmaf(r, e[u + 1],  o1);
            } else {
                e[u]     = fmaf(r, e[u],      o0);
                e[u + 1] = fmaf(r, e[u + 1], -o1);
            }
        }
    }
}

// gray decode (p such that p ^ (p>>1) = g)
__device__ __host__ __forceinline__ int gdec(int g) {
    int p = g;
    p ^= p >> 1; p ^= p >> 2; p ^= p >> 4; p ^= p >> 8; p ^= p >> 16;
    return p;
}
__device__ __forceinline__ int gd6(int u) {
    int p = u; p ^= p >> 1; p ^= p >> 2; p ^= p >> 4; return p & 63;
}

// ---------------------------------------------------------------------------
// HH kernel: (R5_l1) * H1 * P * (H0 x R5_l0). Orbit = g bits 19:14 in regs;
// pos bit 13 on lane bit 0. Single-wave grid-stride over 1024 units.
// ---------------------------------------------------------------------------
__global__ void __launch_bounds__(256, 2) hh_kernel(const float* __restrict__ in,
                                                    float* __restrict__ out) {
    cudaGridDependencySynchronize();       // PDL: wait before reading any global
    const int tid = threadIdx.x;
    const int t0  = tid & 1;
    const int w   = tid >> 5;                     // 0..7
    const int tl  = (tid >> 1) & 15;              // pos bits 3:0
    const float2* rf0 = g_rf;           // layer 0
    const float2* rf1 = g_rf + NQ;      // layer 1

    for (int blk = blockIdx.x; blk < NUNITS; blk += gridDim.x) {
        const int sub = blk & 63;
        const int pos = (t0 << 13) | (sub << 7) | (w << 4) | tl;
        const size_t bbase = (size_t)(blk >> 6) << 20;

        float e[64];
        const float* pin = in + bbase + pos;
#pragma unroll
        for (int u = 0; u < 64; u++) e[u] = pin[u << 14];

        // layer-0 high stages (g-domain, plain): qubit q at u bit (5-q)
        stage_fg<64>(e, 32, rf0[0]);
        stage_fg<64>(e, 16, rf0[1]);
        stage_fg<64>(e,  8, rf0[2]);
        stage_fg<64>(e,  4, rf0[3]);
        stage_fg<64>(e,  2, rf0[4]);
        stage_fg<64>(e,  1, rf0[5]);

        // conj(H1): qubit q -> HB = 5-q
        conj_stage<5>(e, rf1[0]);
        conj_stage<4>(e, rf1[1]);
        conj_stage<3>(e, rf1[2]);
        conj_stage<2>(e, rf1[3]);
        conj_stage<1>(e, rf1[4]);
        conj_r5_stage(e, rf1[5]);

        // scatter with P
        const int A = gdec(pos);
        float* pa = out + bbase + A;
        float* pb = out + bbase + (A ^ 0x3FFF);
#pragma unroll
        for (int u = 0; u < 64; u++) {
            int hi = gd6(u) << 14;
            if (__popc(u) & 1) pb[hi] = e[u];
            else               pa[hi] = e[u];
        }
    }
}

// ---------------------------------------------------------------------------
// PH kernel: (H_l x R5_l) * P over qubits 0..5 (64-element orbit).
// Gather at g = ((k<<14)^(k<<13)) ^ (pos^(pos>>1)). Single-wave grid-stride.
// ---------------------------------------------------------------------------
__global__ void __launch_bounds__(256, 2) ph_kernel(const float* __restrict__ in,
                                                    float* __restrict__ out,
                                                    int layer) {
    cudaGridDependencySynchronize();       // PDL
    const float2* rf = g_rf + layer * NQ;

    for (int blk = blockIdx.x; blk < NUNITS; blk += gridDim.x) {
        const int pos = (blk & 63) * 256 + threadIdx.x;   // 14-bit position
        const size_t bbase = (size_t)(blk >> 6) << 20;
        const int G = pos ^ (pos >> 1);

        float e[64];
        const float* pin = in + bbase;
#pragma unroll
        for (int k = 0; k < 64; k++)
            e[k] = pin[((k << 14) ^ (k << 13)) ^ G];

        stage_fg<64>(e, 32, rf[0]);
        stage_fg<64>(e, 16, rf[1]);
        stage_fg<64>(e,  8, rf[2]);
        stage_fg<64>(e,  4, rf[3]);
        stage_fg<64>(e,  2, rf[4]);
        stage_fg<64>(e,  1, rf[5]);

        float* pout = out + bbase + pos;
#pragma unroll
        for (int k = 0; k < 64; k++) pout[k << 14] = e[k];
    }
}

// ---------------------------------------------------------------------------
// LOW14 kernel: qubits 6..19 inside contiguous 16384-float tiles.
// 512 threads x 32 regs, 64 KB smem -> 2 CTAs/SM. Single-wave grid-stride.
// idx = j*512 + w*32 + t (j: bits 13:9, w: 8:5, t: 4:0); idx bit b <-> qubit 19-b.
// Phase1: shuffles q19..15; reg stages q6..10. Transpose swaps j[3:0] <-> w.
// Phase2: reg stages q11..14. FINAL folds last P + abs*|C| into scatter.
// ---------------------------------------------------------------------------
template <bool FINAL>
__global__ void __launch_bounds__(512, 2) low14_kernel(const float* in,
                                                       float* out,
                                                       int layer) {
    cudaGridDependencySynchronize();       // PDL
    extern __shared__ float sm[];          // 16384 floats = 64 KB
    const int t = threadIdx.x & 31;
    const int w = threadIdx.x >> 5;        // 0..15
    const float2* rf = g_rf + layer * NQ;

    for (int blk = blockIdx.x; blk < NUNITS; blk += gridDim.x) {
        const int tile = blk & 63;
        const size_t bbase = (size_t)(blk >> 6) << 20;
        const size_t tbase = bbase + ((size_t)tile << 14);

        float e[32];
        const float* p = in + tbase;
#pragma unroll
        for (int j = 0; j < 32; j++) e[j] = p[j * 512 + w * 32 + t];

        stage_xlane_fg(e, 0, rf[19], t);
        stage_xlane_fg(e, 1, rf[18], t);
        stage_xlane_fg(e, 2, rf[17], t);
        stage_xlane_fg(e, 3, rf[16], t);
        stage_xlane_fg(e, 4, rf[15], t);
        stage_fg<32>(e, 16, rf[6]);
        stage_fg<32>(e,  8, rf[7]);
        stage_fg<32>(e,  4, rf[8]);
        stage_fg<32>(e,  2, rf[9]);
        stage_fg<32>(e,  1, rf[10]);

        __syncthreads();                   // guard smem reuse across loop iters
#pragma unroll
        for (int j = 0; j < 32; j++) sm[j * 512 + w * 32 + t] = e[j];
        __syncthreads();
#pragma unroll
        for (int j = 0; j < 32; j++)
            e[j] = sm[(j >> 4) * 8192 + w * 512 + (j & 15) * 32 + t];

        // now e[j]: idx = ((j>>4)<<13) | (w<<9) | ((j&15)<<5) | t
        stage_fg<32>(e, 8, rf[11]);
        stage_fg<32>(e, 4, rf[12]);
        stage_fg<32>(e, 2, rf[13]);
        stage_fg<32>(e, 1, rf[14]);

        if (FINAL) {
            const int   pbase = gdec((tile << 14) | (w << 9) | t);
            const float absC  = g_absC;
#pragma unroll
            for (int j = 0; j < 32; j++) {
                int cj = gdec(((j >> 4) << 13) | ((j & 15) << 5));  // const per j
                out[bbase + (pbase ^ cj)] = fabsf(e[j]) * absC;
            }
        } else {
            float* q = out + tbase;
#pragma unroll
            for (int j = 0; j < 32; j++)
                q[(j >> 4) * 8192 + w * 512 + (j & 15) * 32 + t] = e[j];
        }
    }
}

// ---------------------------------------------------------------------------
// Host: de-chunked 7-pass pipeline, single-wave grids, PDL on every boundary.
// ---------------------------------------------------------------------------
static cudaLaunchAttribute g_pdl_attr[1];

static inline cudaLaunchConfig_t mkcfg(unsigned grid, unsigned block, size_t smem) {
    cudaLaunchConfig_t c{};
    c.gridDim  = dim3(grid, 1, 1);
    c.blockDim = dim3(block, 1, 1);
    c.dynamicSmemBytes = smem;
    c.stream = 0;
    g_pdl_attr[0].id = cudaLaunchAttributeProgrammaticStreamSerialization;
    g_pdl_attr[0].val.programmaticStreamSerializationAllowed = 1;
    c.attrs = g_pdl_attr;
    c.numAttrs = 1;
    return c;
}

extern "C" void kernel_launch(void* const* d_in, const int* in_sizes, int n_in,
                              void* d_out, int out_size) {
    const float* x     = (const float*)d_in[0];
    const float* theta = (const float*)d_in[1];
    float*       out   = (float*)d_out;

    float *bA = nullptr, *bB = nullptr;
    cudaGetSymbolAddress((void**)&bA, g_bufA);
    cudaGetSymbolAddress((void**)&bB, g_bufB);

    const int SM14 = 16384 * sizeof(float);
    cudaFuncSetAttribute(low14_kernel<false>, cudaFuncAttributeMaxDynamicSharedMemorySize, SM14);
    cudaFuncSetAttribute(low14_kernel<true>,  cudaFuncAttributeMaxDynamicSharedMemorySize, SM14);

    sincos_kernel<<<1, 128>>>(theta);

    cudaLaunchConfig_t cL = mkcfg(GRID1W, 512, SM14);  // low14
    cudaLaunchConfig_t cH = mkcfg(GRID1W, 256, 0);     // hh / ph

    cudaLaunchKernelEx(&cL, low14_kernel<false>, x, bA, 0);                // L0
    cudaLaunchKernelEx(&cH, hh_kernel, (const float*)bA, bB);              // H1*P*H0'
    cudaLaunchKernelEx(&cL, low14_kernel<false>, (const float*)bB, bB, 1); // L1 (in-place)
    cudaLaunchKernelEx(&cH, ph_kernel, (const float*)bB, bA, 2);           // (H2,R5l2)*P
    cudaLaunchKernelEx(&cL, low14_kernel<false>, (const float*)bA, bA, 2); // L2 (in-place)
    cudaLaunchKernelEx(&cH, ph_kernel, (const float*)bA, bB, 3);           // (H3,R5l3)*P
    cudaLaunchKernelEx(&cL, low14_kernel<true>,  (const float*)bB, out, 3); // P*L3
}

// round 15
// speedup vs baseline: 1.0577x; 1.0577x over previous
#include <cuda_runtime.h>
#include <math.h>
#include <stdint.h>

#define NQ    20
#define NL    4
#define BATCH 16
#define DIM   (1 << NQ)

__device__ float  g_bufA[BATCH * DIM];   // 64 MB
__device__ float  g_bufB[BATCH * DIM];   // 64 MB
__device__ float2 g_rf[NL * NQ];   // .x = ratio (|r|<=1), .y = form (0 or 1)
__device__ float  g_absC;          // |product of per-gate scales|

// ---------------------------------------------------------------------------
// Fast-Givens precompute.
//   form0 (|c|>=|s|): M = c*[[1,-t],[t,1]], t=s/c
//   form1 (|s|> |c|): M = s*[[u,-1],[1,u]], u=c/s
// ---------------------------------------------------------------------------
__global__ void sincos_kernel(const float* __restrict__ theta) {
    __shared__ float sc[NL * NQ];
    int i = threadIdx.x;
    if (i < NL * NQ) {
        float t = 0.5f * theta[i];
        float c = cosf(t), s = sinf(t);
        bool form = fabsf(s) > fabsf(c);
        g_rf[i] = make_float2(form ? (c / s) : (s / c), form ? 1.0f : 0.0f);
        sc[i] = form ? s : c;
    }
    __syncthreads();
    if (i == 0) {
        float p = 1.0f;
        for (int k = 0; k < NL * NQ; k++) p *= sc[k];
        g_absC = fabsf(p);
    }
}

// ---------------------------------------------------------------------------
// Fast-Givens butterflies. 'a' = role-0 element:
//   form0: a' = a - r*b ; b' = b + r*a
//   form1: a' = r*a - b ; b' = r*b + a
// ---------------------------------------------------------------------------
template <int N>
__device__ __forceinline__ void stage_fg(float* e, int m, float2 rf) {
    float r = rf.x;
    if (rf.y == 0.0f) {
#pragma unroll
        for (int j = 0; j < N; j++)
            if ((j & m) == 0) {
                float a = e[j], b = e[j | m];
                e[j]     = fmaf(-r, b, a);
                e[j | m] = fmaf( r, a, b);
            }
    } else {
#pragma unroll
        for (int j = 0; j < N; j++)
            if ((j & m) == 0) {
                float a = e[j], b = e[j | m];
                e[j]     = fmaf(r, a, -b);
                e[j | m] = fmaf(r, b,  a);
            }
    }
}

__device__ __forceinline__ float xsign(float v, uint32_t sg) {
    return __uint_as_float(__float_as_uint(v) ^ sg);
}

// Conjugated H stage (P^-1 H P): couples u-pairs differing in bits {hb, hb-1};
// role(u) = parity(u >> hb).
template <int HB>
__device__ __forceinline__ void conj_stage(float e[64], float2 rf) {
    const int mask = 3 << (HB - 1);
    float r = rf.x;
    bool f1 = (rf.y != 0.0f);
    if (!f1) {
#pragma unroll
        for (int u = 0; u < 64; u++)
            if ((u & (1 << HB)) == 0) {
                int v = u ^ mask;
                int ra = __popc(u >> HB) & 1;
                int ia = ra ? v : u;
                int ib = ra ? u : v;
                float a = e[ia], b = e[ib];
                e[ia] = fmaf(-r, b, a);
                e[ib] = fmaf( r, a, b);
            }
    } else {
#pragma unroll
        for (int u = 0; u < 64; u++)
            if ((u & (1 << HB)) == 0) {
                int v = u ^ mask;
                int ra = __popc(u >> HB) & 1;
                int ia = ra ? v : u;
                int ib = ra ? u : v;
                float a = e[ia], b = e[ib];
                e[ia] = fmaf(r, a, -b);
                e[ib] = fmaf(r, b,  a);
            }
    }
}

// Conjugated R5(layer1) stage inside hh: couples g bits {14,13} = (reg bit 0,
// lane bit 0). Partner of e[u] is shfl_xor(e[u^1], 1). Role 'a' = parity(u)==0.
__device__ __forceinline__ void conj_r5_stage(float e[64], float2 rf) {
    float r = rf.x;
    bool f1 = (rf.y != 0.0f);
#pragma unroll
    for (int u = 0; u < 64; u += 2) {
        float o0 = __shfl_xor_sync(0xffffffffu, e[u + 1], 1);
        float o1 = __shfl_xor_sync(0xffffffffu, e[u],     1);
        bool aFirst = ((__popc(u) & 1) == 0);
        if (!f1) {
            if (aFirst) {
                e[u]     = fmaf(-r, o0, e[u]);
                e[u + 1] = fmaf( r, o1, e[u + 1]);
            } else {
                e[u]     = fmaf( r, o0, e[u]);
                e[u + 1] = fmaf(-r, o1, e[u + 1]);
            }
        } else {
            if (aFirst) {
                e[u]     = fmaf(r, e[u],     -o0);
                e[u + 1] = fmaf(r, e[u + 1],  o1);
            } else {
                e[u]     = fmaf(r, e[u],      o0);
                e[u + 1] = fmaf(r, e[u + 1], -o1);
            }
        }
    }
}

// gray decode (p such that p ^ (p>>1) = g)
__device__ __host__ __forceinline__ int gdec(int g) {
    int p = g;
    p ^= p >> 1; p ^= p >> 2; p ^= p >> 4; p ^= p >> 8; p ^= p >> 16;
    return p;
}
__device__ __forceinline__ int gd6(int u) {
    int p = u; p ^= p >> 1; p ^= p >> 2; p ^= p >> 4; return p & 63;
}

// ---------------------------------------------------------------------------
// HH kernel: (R5_l1) * H1 * P * (H0 x R5_l0). Orbit = g bits 19:14 in regs;
// pos bit 13 on lane bit 0.  pos = (t0<<13)|(sub<<7)|(w<<4)|t[4:1], grid 1024.
// ---------------------------------------------------------------------------
__global__ void __launch_bounds__(256, 2) hh_kernel(const float* __restrict__ in,
                                                    float* __restrict__ out) {
    cudaGridDependencySynchronize();       // PDL
    const int blk = blockIdx.x;                   // BATCH*64
    const int tid = threadIdx.x;
    const int t0  = tid & 1;
    const int w   = tid >> 5;                     // 0..7
    const int tl  = (tid >> 1) & 15;              // pos bits 3:0
    const int sub = blk & 63;
    const int pos = (t0 << 13) | (sub << 7) | (w << 4) | tl;
    const size_t bbase = (size_t)(blk >> 6) << 20;

    float e[64];
    const float* pin = in + bbase + pos;
#pragma unroll
    for (int u = 0; u < 64; u++) e[u] = pin[u << 14];

    const float2* rf0 = g_rf;           // layer 0
    const float2* rf1 = g_rf + NQ;      // layer 1

    stage_fg<64>(e, 32, rf0[0]);
    stage_fg<64>(e, 16, rf0[1]);
    stage_fg<64>(e,  8, rf0[2]);
    stage_fg<64>(e,  4, rf0[3]);
    stage_fg<64>(e,  2, rf0[4]);
    stage_fg<64>(e,  1, rf0[5]);

    conj_stage<5>(e, rf1[0]);
    conj_stage<4>(e, rf1[1]);
    conj_stage<3>(e, rf1[2]);
    conj_stage<2>(e, rf1[3]);
    conj_stage<1>(e, rf1[4]);
    conj_r5_stage(e, rf1[5]);

    const int A = gdec(pos);
    float* pa = out + bbase + A;
    float* pb = out + bbase + (A ^ 0x3FFF);
#pragma unroll
    for (int u = 0; u < 64; u++) {
        int hi = gd6(u) << 14;
        if (__popc(u) & 1) pb[hi] = e[u];
        else               pa[hi] = e[u];
    }
}

// ---------------------------------------------------------------------------
// PH kernel: (H_l x R5_l) * P over qubits 0..5 (64-element orbit), grid 1024.
// ---------------------------------------------------------------------------
__global__ void __launch_bounds__(256, 2) ph_kernel(const float* __restrict__ in,
                                                    float* __restrict__ out,
                                                    int layer) {
    cudaGridDependencySynchronize();       // PDL
    const int blk = blockIdx.x;                   // BATCH*64
    const int pos = (blk & 63) * 256 + threadIdx.x;   // 14-bit position
    const size_t bbase = (size_t)(blk >> 6) << 20;
    const int G = pos ^ (pos >> 1);

    float e[64];
    const float* pin = in + bbase;
#pragma unroll
    for (int k = 0; k < 64; k++)
        e[k] = pin[((k << 14) ^ (k << 13)) ^ G];

    const float2* rf = g_rf + layer * NQ;
    stage_fg<64>(e, 32, rf[0]);
    stage_fg<64>(e, 16, rf[1]);
    stage_fg<64>(e,  8, rf[2]);
    stage_fg<64>(e,  4, rf[3]);
    stage_fg<64>(e,  2, rf[4]);
    stage_fg<64>(e,  1, rf[5]);

    float* pout = out + bbase + pos;
#pragma unroll
    for (int k = 0; k < 64; k++) pout[k << 14] = e[k];
}

// ---------------------------------------------------------------------------
// LOW14 zero-shuffle kernel: qubits 6..19 in 16384-float tiles. 512 thr x 32
// regs, 64 KB smem, 2 CTAs/SM, grid 1024. Three register phases, two XOR-
// swizzled smem transposes, no warp shuffles.
//  L1: idx = (j@13:9, w@8:5, t@4:0)  -> phase1: q6..10 on j
//  T1 (j<->t): store phys (j<<9)|(w<<5)|(t^j); load (t<<9)|(w<<5)|(j^t)
//  L2: idx = (t@13:9, w@8:5, j@4:0)  -> phase2: q19..15 on j
//  T2: store back at same phys; load element (w<<10)|(j4<<9)|(jl<<5)|t from
//      phys (key<<9)|(jl<<5)|(t^key), key = (w<<1)|(j>>4)
//  L3: idx = (w@13:10, j4@9, j[3:0]@8:5, t@4:0) -> phase3: q14..11 on j[3:0]
//  Store lane-contiguous; FINAL folds P + abs*|C| (gdec over disjoint fields).
// ---------------------------------------------------------------------------
template <bool FINAL>
__global__ void __launch_bounds__(512, 2) low14_kernel(const float* in,
                                                       float* out,
                                                       int layer) {
    cudaGridDependencySynchronize();       // PDL
    extern __shared__ float sm[];          // 16384 floats = 64 KB
    const int t = threadIdx.x & 31;
    const int w = threadIdx.x >> 5;        // 0..15
    const int blk = blockIdx.x;            // BATCH*64
    const int tile = blk & 63;
    const size_t bbase = (size_t)(blk >> 6) << 20;
    const size_t tbase = bbase + ((size_t)tile << 14);

    float e[32];
    const float* p = in + tbase;
#pragma unroll
    for (int j = 0; j < 32; j++) e[j] = p[(j << 9) | (w << 5) | t];

    const float2* rf = g_rf + layer * NQ;
    // phase1: q6..10 on j (L1)
    stage_fg<32>(e, 16, rf[6]);
    stage_fg<32>(e,  8, rf[7]);
    stage_fg<32>(e,  4, rf[8]);
    stage_fg<32>(e,  2, rf[9]);
    stage_fg<32>(e,  1, rf[10]);

    // T1: j <-> t
#pragma unroll
    for (int j = 0; j < 32; j++) sm[(j << 9) | (w << 5) | (t ^ j)] = e[j];
    __syncthreads();
#pragma unroll
    for (int j = 0; j < 32; j++) e[j] = sm[(t << 9) | (w << 5) | (j ^ t)];

    // phase2: q19..15 on j (L2)
    stage_fg<32>(e, 1,  rf[19]);
    stage_fg<32>(e, 2,  rf[18]);
    stage_fg<32>(e, 4,  rf[17]);
    stage_fg<32>(e, 8,  rf[16]);
    stage_fg<32>(e, 16, rf[15]);

    // T2: bring w-field into j[3:0]
    __syncthreads();                       // all T1 loads done before overwrite
#pragma unroll
    for (int j = 0; j < 32; j++) sm[(t << 9) | (w << 5) | (j ^ t)] = e[j];
    __syncthreads();
#pragma unroll
    for (int j = 0; j < 32; j++) {
        int key = ((w << 1) | (j >> 4)) & 31;
        e[j] = sm[(key << 9) | ((j & 15) << 5) | (t ^ key)];
    }

    // phase3: q14..11 on j[3:0] (L3); j[4] inert (q10 done in phase1)
    stage_fg<32>(e, 1, rf[14]);
    stage_fg<32>(e, 2, rf[13]);
    stage_fg<32>(e, 4, rf[12]);
    stage_fg<32>(e, 8, rf[11]);

    if (FINAL) {
        const int   pbase = gdec((tile << 14) | (w << 10) | t);
        const float absC  = g_absC;
#pragma unroll
        for (int j = 0; j < 32; j++) {
            int cj = gdec(((j >> 4) << 9) | ((j & 15) << 5));  // const per j
            out[bbase + (pbase ^ cj)] = fabsf(e[j]) * absC;
        }
    } else {
        float* q = out + tbase;
#pragma unroll
        for (int j = 0; j < 32; j++)
            q[(w << 10) | ((j >> 4) << 9) | ((j & 15) << 5) | t] = e[j];
    }
}

// ---------------------------------------------------------------------------
// Host: de-chunked 7-pass pipeline, grid 1024 (multi-wave), PDL boundaries.
// ---------------------------------------------------------------------------
static cudaLaunchAttribute g_pdl_attr[1];

static inline cudaLaunchConfig_t mkcfg(unsigned grid, unsigned block, size_t smem) {
    cudaLaunchConfig_t c{};
    c.gridDim  = dim3(grid, 1, 1);
    c.blockDim = dim3(block, 1, 1);
    c.dynamicSmemBytes = smem;
    c.stream = 0;
    g_pdl_attr[0].id = cudaLaunchAttributeProgrammaticStreamSerialization;
    g_pdl_attr[0].val.programmaticStreamSerializationAllowed = 1;
    c.attrs = g_pdl_attr;
    c.numAttrs = 1;
    return c;
}

extern "C" void kernel_launch(void* const* d_in, const int* in_sizes, int n_in,
                              void* d_out, int out_size) {
    const float* x     = (const float*)d_in[0];
    const float* theta = (const float*)d_in[1];
    float*       out   = (float*)d_out;

    float *bA = nullptr, *bB = nullptr;
    cudaGetSymbolAddress((void**)&bA, g_bufA);
    cudaGetSymbolAddress((void**)&bB, g_bufB);

    const int SM14 = 16384 * sizeof(float);
    cudaFuncSetAttribute(low14_kernel<false>, cudaFuncAttributeMaxDynamicSharedMemorySize, SM14);
    cudaFuncSetAttribute(low14_kernel<true>,  cudaFuncAttributeMaxDynamicSharedMemorySize, SM14);

    sincos_kernel<<<1, 128>>>(theta);

    const int G = BATCH * 64;   // 1024 blocks for every pass

    cudaLaunchConfig_t cL = mkcfg(G, 512, SM14);  // low14
    cudaLaunchConfig_t cH = mkcfg(G, 256, 0);     // hh / ph

    cudaLaunchKernelEx(&cL, low14_kernel<false>, x, bA, 0);                // L0
    cudaLaunchKernelEx(&cH, hh_kernel, (const float*)bA, bB);              // H1*P*H0'
    cudaLaunchKernelEx(&cL, low14_kernel<false>, (const float*)bB, bB, 1); // L1 (in-place)
    cudaLaunchKernelEx(&cH, ph_kernel, (const float*)bB, bA, 2);           // (H2,R5l2)*P
    cudaLaunchKernelEx(&cL, low14_kernel<false>, (const float*)bA, bA, 2); // L2 (in-place)
    cudaLaunchKernelEx(&cH, ph_kernel, (const float*)bA, bB, 3);           // (H3,R5l3)*P
    cudaLaunchKernelEx(&cL, low14_kernel<true>,  (const float*)bB, out, 3); // P*L3
}